// round 12
// baseline (speedup 1.0000x reference)
#include <cuda_runtime.h>
#include <cstdint>

// ---------------------------------------------------------------------------
// WindowAttention (Swin-style), GB300 sm_103a — fused kernel, R12.
// Base = R11. Change: K stored TRANSPOSED (sKT[chan][token], stride 72) so
// phase-B B-fragment loads are conflict-free (the old layout had an 8-way
// bank conflict: key stride 8*136 ≡ 0 mod 32 banks).
// Weights fragment-linear in global (coalesced LDG.64 per B-fragment).
// ---------------------------------------------------------------------------

__device__ uint32_t g_wqkvF[48 * 16 * 64];   // [n8][step][lane*2] fragment-linear
__device__ uint32_t g_woutF[16 * 16 * 64];

__device__ __forceinline__ uint32_t f2tf(float f) {
    uint32_t r;
    asm("cvt.rna.tf32.f32 %0, %1;" : "=r"(r) : "f"(f));
    return r;
}

__device__ __forceinline__ void mma8(float* c, const uint32_t* a, const uint32_t* b) {
    asm volatile(
        "mma.sync.aligned.m16n8k8.row.col.f32.tf32.tf32.f32 "
        "{%0,%1,%2,%3}, {%4,%5,%6,%7}, {%8,%9}, {%0,%1,%2,%3};\n"
        : "+f"(c[0]), "+f"(c[1]), "+f"(c[2]), "+f"(c[3])
        : "r"(a[0]), "r"(a[1]), "r"(a[2]), "r"(a[3]), "r"(b[0]), "r"(b[1]));
}
// slot within an 8-wide k-group: [k0 k4 k1 k5 k2 k6 k3 k7]
__device__ __forceinline__ int SL(int c) { return ((c & 3) << 1) | (c >> 2); }

// ===========================================================================
// cvt: weights -> tf32 fragment-linear layout.
// fragment element (n8, step, lane, j):  n = n8*8 + (lane>>2),
//                                        k = step*8 + (lane&3) + 4*j
// ===========================================================================
__global__ void cvt_kernel(const float* __restrict__ wqkv,
                           const float* __restrict__ wout) {
    int i = blockIdx.x * 256 + threadIdx.x;   // 0..49151
    {
        int n8 = i >> 10, rem = i & 1023;
        int step = rem >> 6, rem2 = rem & 63;
        int lane = rem2 >> 1, j = rem2 & 1;
        int n = n8 * 8 + (lane >> 2);
        int k = step * 8 + (lane & 3) + 4 * j;
        g_wqkvF[i] = f2tf(wqkv[k * 384 + n]);
    }
    if (i < 16 * 16 * 64) {
        int n8 = i >> 10, rem = i & 1023;
        int step = rem >> 6, rem2 = rem & 63;
        int lane = rem2 >> 1, j = rem2 & 1;
        int n = n8 * 8 + (lane >> 2);
        int k = step * 8 + (lane & 3) + 4 * j;
        g_woutF[i] = f2tf(wout[k * 128 + n]);
    }
}

// ===========================================================================
// smem map (u32):
//  sQ  0..8704      [64 tok][136] k-paired
//  sKT 8704..17920  [128 chan][72] token-major (transposed K)
//  sV  17920..26624 [64 tok][136] d-paired
//  sA  26624..35328 (phase 1 A; later sO)
//  sP  35328..53760 (4 heads x [64][72])
//  PE  53760..54016   BO 54016..54144
//  total 54144 u32 = 216576 B
// ===========================================================================
#define SQ_OFF  0
#define SKT_OFF 8704
#define SV_OFF  17920
#define SA_OFF  26624
#define SP_OFF  35328
#define PE_OFF  53760
#define BO_OFF  54016
#define FU_SMEM (54144 * 4)

__global__ __launch_bounds__(512, 1)
void fused_kernel(const float* __restrict__ x,
                  const float* __restrict__ bout,
                  const float* __restrict__ pe,  const float* __restrict__ ul,
                  const float* __restrict__ lr,  float* __restrict__ out) {
    extern __shared__ uint32_t sm[];
    uint32_t* sQ  = sm + SQ_OFF;
    uint32_t* sKT = sm + SKT_OFF;
    uint32_t* sV  = sm + SV_OFF;
    uint32_t* sA  = sm + SA_OFF;
    uint32_t* sP  = sm + SP_OFF;
    uint32_t* sO  = sm + SA_OFF;    // overlays sA (dead after phase 1)
    float* sPE = (float*)(sm + PE_OFF);
    float* sBO = (float*)(sm + BO_OFF);

    const int t = threadIdx.x;
    const int warp = t >> 5, lane = t & 31;
    const int gid = lane >> 2, tid4 = lane & 3;
    const int blk = blockIdx.x;
    const int bb = blk >> 8, win = blk & 255;
    const int wy = win >> 4, wx = win & 15;

    // ---- Phase 1 setup: warp tile 32 x 48 (grid 2 M x 8 N) ----
    const int gwm = warp & 1, gwn = warp >> 1;
    const int rowb1 = gwm * 32;

    // B fragment loader: fragment-linear, one coalesced LDG.64 per fragment
    uint2 bA[12], bB[12];
    auto ldBkt = [&](uint2* dst, int kt) {
        #pragma unroll
        for (int kk = 0; kk < 2; kk++) {
            int step = kt * 2 + kk;
            #pragma unroll
            for (int nt = 0; nt < 6; nt++) {
                int n8g = gwn * 6 + nt;
                dst[kk * 6 + nt] =
                    *(const uint2*)&g_wqkvF[(n8g * 16 + step) * 64 + lane * 2];
            }
        }
    };
    ldBkt(bA, 0);
    ldBkt(bB, 1);

    // ---- A gather: rolled x rows, tf32, pair-interleaved, packed STS.64 ----
    {
        const int row_a = t >> 3, part = t & 7;
        const int ty = row_a >> 3, tx = row_a & 7;
        const int sh = (wy * 8 + ty + 4) & 127, sw = (wx * 8 + tx + 4) & 127;
        const float* aptr = x + (((size_t)bb * 128 + sh) * 128 + sw) * 128 + part * 16;
        uint32_t* ap = sA + row_a * 136 + part * 16;
        float4 v0 = *(const float4*)(aptr + 0);
        float4 v1 = *(const float4*)(aptr + 4);
        float4 v2 = *(const float4*)(aptr + 8);
        float4 v3 = *(const float4*)(aptr + 12);
        *(uint2*)&ap[0]  = make_uint2(f2tf(v0.x), f2tf(v1.x));
        *(uint2*)&ap[2]  = make_uint2(f2tf(v0.y), f2tf(v1.y));
        *(uint2*)&ap[4]  = make_uint2(f2tf(v0.z), f2tf(v1.z));
        *(uint2*)&ap[6]  = make_uint2(f2tf(v0.w), f2tf(v1.w));
        *(uint2*)&ap[8]  = make_uint2(f2tf(v2.x), f2tf(v3.x));
        *(uint2*)&ap[10] = make_uint2(f2tf(v2.y), f2tf(v3.y));
        *(uint2*)&ap[12] = make_uint2(f2tf(v2.z), f2tf(v3.z));
        *(uint2*)&ap[14] = make_uint2(f2tf(v2.w), f2tf(v3.w));
    }
    if (t < 225) sPE[t] = pe[t];
    if (t < 128) sBO[t] = bout[t];
    __syncthreads();                         // [FULL SYNC 1] sA/sPE/sBO ready

    // ---- Phase 1: QKV GEMM, barrier-free mainloop, A double-buffered ----
    float acc[2][6][4];
    #pragma unroll
    for (int a = 0; a < 2; a++)
        #pragma unroll
        for (int b2 = 0; b2 < 6; b2++)
            #pragma unroll
            for (int c = 0; c < 4; c++) acc[a][b2][c] = 0.f;

    const uint32_t* aR0 = &sA[(rowb1 + gid) * 136 + 2 * tid4];
    const uint32_t* aR1 = aR0 + 8 * 136;
    const uint32_t* aR2 = aR0 + 16 * 136;
    const uint32_t* aR3 = aR0 + 24 * 136;
    uint2 aF[2][4];
    auto ldA = [&](uint2* d, int step) {
        int ka = step * 8;
        d[0] = *(const uint2*)(aR0 + ka);
        d[1] = *(const uint2*)(aR1 + ka);
        d[2] = *(const uint2*)(aR2 + ka);
        d[3] = *(const uint2*)(aR3 + ka);
    };
    ldA(aF[0], 0);

    #pragma unroll
    for (int step = 0; step < 16; step++) {
        if (step + 1 < 16) ldA(aF[(step + 1) & 1], step + 1);
        const uint2* bfk = (((step >> 1) & 1) ? bB : bA) + (step & 1) * 6;
        const uint2* af = aF[step & 1];
        uint32_t am0[4] = {af[0].x, af[1].x, af[0].y, af[1].y};
        uint32_t am1[4] = {af[2].x, af[3].x, af[2].y, af[3].y};
        #pragma unroll
        for (int nt = 0; nt < 6; nt++) {
            mma8(acc[0][nt], am0, (const uint32_t*)&bfk[nt]);
            mma8(acc[1][nt], am1, (const uint32_t*)&bfk[nt]);
        }
        if ((step & 1) == 1) {
            int kt = step >> 1;
            if (kt + 2 < 8) ldBkt((kt & 1) ? bB : bA, kt + 2);
        }
    }

    // epilogue: Q -> sQ (paired), K -> sKT (transposed), V -> sV (paired)
    {
        const int s0 = SL(2 * tid4), s1 = SL(2 * tid4 + 1);
        #pragma unroll
        for (int mt = 0; mt < 2; mt++) {
            int r0 = rowb1 + mt * 16 + gid, r1 = r0 + 8;
            #pragma unroll
            for (int nt = 0; nt < 6; nt++) {
                int gcol = gwn * 48 + nt * 8;
                if (gcol < 128) {                    // Q segment
                    uint32_t* dst = sQ + gcol;
                    dst[r0 * 136 + s0] = f2tf(acc[mt][nt][0]);
                    dst[r0 * 136 + s1] = f2tf(acc[mt][nt][1]);
                    dst[r1 * 136 + s0] = f2tf(acc[mt][nt][2]);
                    dst[r1 * 136 + s1] = f2tf(acc[mt][nt][3]);
                } else if (gcol < 256) {             // K segment -> transposed
                    int c0 = gcol - 128 + 2 * tid4;
                    sKT[c0 * 72 + r0]       = f2tf(acc[mt][nt][0]);
                    sKT[(c0 + 1) * 72 + r0] = f2tf(acc[mt][nt][1]);
                    sKT[c0 * 72 + r1]       = f2tf(acc[mt][nt][2]);
                    sKT[(c0 + 1) * 72 + r1] = f2tf(acc[mt][nt][3]);
                } else {                             // V segment
                    uint32_t* dst = sV + (gcol - 256);
                    dst[r0 * 136 + s0] = f2tf(acc[mt][nt][0]);
                    dst[r0 * 136 + s1] = f2tf(acc[mt][nt][1]);
                    dst[r1 * 136 + s0] = f2tf(acc[mt][nt][2]);
                    dst[r1 * 136 + s1] = f2tf(acc[mt][nt][3]);
                }
            }
        }
    }
    __syncthreads();                         // [FULL SYNC 2] Q/K/V visible

    // ---- Phase B: S = Q K^T (4 warps/head, 16 q-rows each) ----
    const int head = warp >> 2;
    const int wrb = (warp & 3) * 16;
    const int hoff = head * 32;
    float sacc[8][4];
    #pragma unroll
    for (int b2 = 0; b2 < 8; b2++)
        #pragma unroll
        for (int c = 0; c < 4; c++) sacc[b2][c] = 0.f;

    {
        const uint32_t* qR0 = &sQ[(wrb + gid) * 136 + hoff + 2 * tid4];
        const uint32_t* qR1 = qR0 + 8 * 136;
        // conflict-free: bank = 8*tid4 + gid (all 32 distinct)
        const uint32_t* kB = &sKT[(hoff + tid4) * 72 + gid];
        #pragma unroll
        for (int kk = 0; kk < 4; kk++) {
            uint2 a0 = *(const uint2*)(qR0 + kk * 8);
            uint2 a1 = *(const uint2*)(qR1 + kk * 8);
            uint32_t a[4] = {a0.x, a1.x, a0.y, a1.y};
            #pragma unroll
            for (int nt = 0; nt < 8; nt++) {
                uint32_t b[2];
                b[0] = kB[(kk * 8) * 72 + nt * 8];
                b[1] = kB[(kk * 8 + 4) * 72 + nt * 8];
                mma8(sacc[nt], a, b);
            }
        }
    }

    // ---- Phase C: bias + masks + softmax ----
    const float scale = 0.17677669529663689f;
    const bool addUL = (wy == 15);
    const bool addLR = (wx == 15);

    #pragma unroll
    for (int rh = 0; rh < 2; rh++) {
        const int i = wrb + rh * 8 + gid;
        const int iy = i >> 3, ix = i & 7;
        float vrow[16];
        float m = -1e30f;
        #pragma unroll
        for (int nt = 0; nt < 8; nt++) {
            #pragma unroll
            for (int u = 0; u < 2; u++) {
                int j = nt * 8 + tid4 * 2 + u;
                int jy = j >> 3, jx = j & 7;
                float v = sacc[nt][rh * 2 + u] * scale
                        + sPE[(jy - iy + 7) * 15 + (jx - ix + 7)];
                if (addUL) v += ul[i * 64 + j];
                if (addLR) v += lr[i * 64 + j];
                vrow[nt * 2 + u] = v;
                m = fmaxf(m, v);
            }
        }
        m = fmaxf(m, __shfl_xor_sync(0xffffffffu, m, 1));
        m = fmaxf(m, __shfl_xor_sync(0xffffffffu, m, 2));
        float sum = 0.f;
        #pragma unroll
        for (int u2 = 0; u2 < 16; u2++) {
            vrow[u2] = __expf(vrow[u2] - m);
            sum += vrow[u2];
        }
        sum += __shfl_xor_sync(0xffffffffu, sum, 1);
        sum += __shfl_xor_sync(0xffffffffu, sum, 2);
        float inv = 1.f / sum;
        #pragma unroll
        for (int nt = 0; nt < 8; nt++) {
            #pragma unroll
            for (int u = 0; u < 2; u++)
                sacc[nt][rh * 2 + u] = vrow[nt * 2 + u] * inv;
        }
    }

    // ---- Phase D: store P (tf32, paired) into sP[head] ----
    uint32_t* myP = sP + head * (64 * 72);
    {
        const int s0 = SL(2 * tid4), s1 = SL(2 * tid4 + 1);
        #pragma unroll
        for (int rh = 0; rh < 2; rh++) {
            int i = wrb + rh * 8 + gid;
            #pragma unroll
            for (int nt = 0; nt < 8; nt++) {
                myP[i * 72 + nt * 8 + s0] = f2tf(sacc[nt][rh * 2]);
                myP[i * 72 + nt * 8 + s1] = f2tf(sacc[nt][rh * 2 + 1]);
            }
        }
    }
    // named barrier: only the 4 warps of this head need sP[head] coherent
    asm volatile("bar.sync %0, %1;" :: "r"(1 + head), "r"(128) : "memory");

    // ---- Phase E: O = P @ V ----
    float oacc[4][4];
    #pragma unroll
    for (int b2 = 0; b2 < 4; b2++)
        #pragma unroll
        for (int c = 0; c < 4; c++) oacc[b2][c] = 0.f;
    const int dslot = SL(gid);

    {
        const uint32_t* pR0 = &myP[(wrb + gid) * 72 + 2 * tid4];
        const uint32_t* pR1 = pR0 + 8 * 72;
        const uint32_t* vB0 = &sV[tid4 * 136 + hoff + dslot];
        const uint32_t* vB1 = vB0 + 4 * 136;
        #pragma unroll
        for (int kk = 0; kk < 8; kk++) {
            uint2 a0 = *(const uint2*)(pR0 + kk * 8);
            uint2 a1 = *(const uint2*)(pR1 + kk * 8);
            uint32_t a[4] = {a0.x, a1.x, a0.y, a1.y};
            #pragma unroll
            for (int nt = 0; nt < 4; nt++) {
                uint32_t b[2];
                b[0] = vB0[kk * (8 * 136) + nt * 8];
                b[1] = vB1[kk * (8 * 136) + nt * 8];
                mma8(oacc[nt], a, b);
            }
        }
    }

    // ---- Phase F: store O (tf32, paired) into sO (overlays sA — dead) ----
    {
        const int s0 = SL(2 * tid4), s1 = SL(2 * tid4 + 1);
        #pragma unroll
        for (int nt = 0; nt < 4; nt++) {
            int grp = hoff + nt * 8;
            sO[(wrb + gid) * 136 + grp + s0]     = f2tf(oacc[nt][0]);
            sO[(wrb + gid) * 136 + grp + s1]     = f2tf(oacc[nt][1]);
            sO[(wrb + 8 + gid) * 136 + grp + s0] = f2tf(oacc[nt][2]);
            sO[(wrb + 8 + gid) * 136 + grp + s1] = f2tf(oacc[nt][3]);
        }
    }
    __syncthreads();                         // [FULL SYNC 3] sO visible

    // ---- Phase G: Y = O @ w_out + b_out (frag LDGs + A lookahead) ----
    const int pwm = warp & 3, pwn = warp >> 2;   // 4x4 grid, tile 16x32
    float yacc[4][4];
    #pragma unroll
    for (int b2 = 0; b2 < 4; b2++)
        #pragma unroll
        for (int c = 0; c < 4; c++) yacc[b2][c] = 0.f;

    const uint32_t* oR0 = &sO[(pwm * 16 + gid) * 136 + 2 * tid4];
    const uint32_t* oR1 = oR0 + 8 * 136;
    uint2 wA[4], wB[4];
    auto ldW = [&](uint2* dst, int kk) {
        #pragma unroll
        for (int nt = 0; nt < 4; nt++) {
            int n8g = pwn * 4 + nt;
            dst[nt] = *(const uint2*)&g_woutF[(n8g * 16 + kk) * 64 + lane * 2];
        }
    };
    uint2 oaF[2][2];
    auto ldOA = [&](uint2* d, int kk) {
        d[0] = *(const uint2*)(oR0 + kk * 8);
        d[1] = *(const uint2*)(oR1 + kk * 8);
    };
    ldW(wA, 0);
    ldW(wB, 1);
    ldOA(oaF[0], 0);

    #pragma unroll
    for (int kk = 0; kk < 16; kk++) {
        if (kk + 1 < 16) ldOA(oaF[(kk + 1) & 1], kk + 1);
        const uint2* wf = (kk & 1) ? wB : wA;
        const uint2* af = oaF[kk & 1];
        uint32_t a[4] = {af[0].x, af[1].x, af[0].y, af[1].y};
        #pragma unroll
        for (int nt = 0; nt < 4; nt++)
            mma8(yacc[nt], a, (const uint32_t*)&wf[nt]);
        if (kk + 2 < 16) {
            if ((kk & 1) == 0) ldW(wA, kk + 2);
            else               ldW(wB, kk + 2);
        }
    }

    #pragma unroll
    for (int rh = 0; rh < 2; rh++) {
        int i = pwm * 16 + rh * 8 + gid;
        int ty = i >> 3, tx = i & 7;
        int h = (wy * 8 + ty + 4) & 127;
        int w = (wx * 8 + tx + 4) & 127;
        float* orow = out + (((size_t)bb * 128 + h) * 128 + w) * 128;
        #pragma unroll
        for (int nt = 0; nt < 4; nt++) {
            int c = pwn * 32 + nt * 8 + tid4 * 2;
            float2 v = make_float2(yacc[nt][rh * 2]     + sBO[c],
                                   yacc[nt][rh * 2 + 1] + sBO[c + 1]);
            *(float2*)(orow + c) = v;
        }
    }
}

// ===========================================================================
extern "C" void kernel_launch(void* const* d_in, const int* in_sizes, int n_in,
                              void* d_out, int out_size) {
    const float* x    = (const float*)d_in[0];
    const float* wqkv = (const float*)d_in[1];
    const float* wout = (const float*)d_in[2];
    const float* bout = (const float*)d_in[3];
    const float* pe   = (const float*)d_in[4];
    const float* ul   = (const float*)d_in[5];
    const float* lr   = (const float*)d_in[6];
    float* out = (float*)d_out;

    cudaFuncSetAttribute(fused_kernel, cudaFuncAttributeMaxDynamicSharedMemorySize, FU_SMEM);

    cvt_kernel<<<192, 256>>>(wqkv, wout);
    fused_kernel<<<4096, 512, FU_SMEM>>>(x, bout, pe, ul, lr, out);
}

// round 13
// speedup vs baseline: 1.0984x; 1.0984x over previous
#include <cuda_runtime.h>
#include <cstdint>

// ---------------------------------------------------------------------------
// WindowAttention (Swin-style), GB300 sm_103a — fused kernel, R13.
// Head-decoupled: each warp computes its own head's Q/K/V slice in P1
// (weights pre-permuted head-major), so heads synchronize via named
// per-head barriers and drift through attention independently.
// Full syncs: 2 (gather, pre-projection). O lives in the per-head sP region.
// Weights fragment-linear in global (coalesced LDG.64 per B-fragment).
// ---------------------------------------------------------------------------

__device__ uint32_t g_wqkvF[48 * 16 * 64];   // head-major [n8'][step][lane*2]
__device__ uint32_t g_woutF[16 * 16 * 64];

__device__ __forceinline__ uint32_t f2tf(float f) {
    uint32_t r;
    asm("cvt.rna.tf32.f32 %0, %1;" : "=r"(r) : "f"(f));
    return r;
}

__device__ __forceinline__ void mma8(float* c, const uint32_t* a, const uint32_t* b) {
    asm volatile(
        "mma.sync.aligned.m16n8k8.row.col.f32.tf32.tf32.f32 "
        "{%0,%1,%2,%3}, {%4,%5,%6,%7}, {%8,%9}, {%0,%1,%2,%3};\n"
        : "+f"(c[0]), "+f"(c[1]), "+f"(c[2]), "+f"(c[3])
        : "r"(a[0]), "r"(a[1]), "r"(a[2]), "r"(a[3]), "r"(b[0]), "r"(b[1]));
}
// slot within an 8-wide k-group: [k0 k4 k1 k5 k2 k6 k3 k7]
__device__ __forceinline__ int SL(int c) { return ((c & 3) << 1) | (c >> 2); }

// ===========================================================================
// cvt: weights -> tf32 fragment-linear.
// wqkv: HEAD-MAJOR permutation. n8' = h*12 + p  (p: 0-3 Q, 4-7 K, 8-11 V).
//   element (n8', step, lane, j): n_orig = seg*128 + h*32 + (p&3)*8 + lane>>2
//                                 k      = step*8 + (lane&3) + 4*j
// wout: unchanged fragment-linear.
// ===========================================================================
__global__ void cvt_kernel(const float* __restrict__ wqkv,
                           const float* __restrict__ wout) {
    int i = blockIdx.x * 256 + threadIdx.x;   // 0..49151
    {
        int n8p = i >> 10, rem = i & 1023;
        int step = rem >> 6, rem2 = rem & 63;
        int lane = rem2 >> 1, j = rem2 & 1;
        int h = n8p / 12, p = n8p % 12;
        int seg = p >> 2;
        int n = seg * 128 + h * 32 + (p & 3) * 8 + (lane >> 2);
        int k = step * 8 + (lane & 3) + 4 * j;
        g_wqkvF[i] = f2tf(wqkv[k * 384 + n]);
    }
    if (i < 16 * 16 * 64) {
        int n8 = i >> 10, rem = i & 1023;
        int step = rem >> 6, rem2 = rem & 63;
        int lane = rem2 >> 1, j = rem2 & 1;
        int n = n8 * 8 + (lane >> 2);
        int k = step * 8 + (lane & 3) + 4 * j;
        g_woutF[i] = f2tf(wout[k * 128 + n]);
    }
}

// ===========================================================================
// smem map (u32):
//  sQ 0..8704   sK 8704..17408   sV 17408..26112   (stride 136, paired)
//  sA 26112..34816  (P1 A; never overlaid — safe during head drift)
//  sP 34816..53248  (4 heads x [64][72]; per-head O overlays own P after E)
//  PE 53248  BO 53504   total 53632 u32 = 214528 B
// ===========================================================================
#define SQ_OFF 0
#define SK_OFF 8704
#define SV_OFF 17408
#define SA_OFF 26112
#define SP_OFF 34816
#define PE_OFF 53248
#define BO_OFF 53504
#define FU_SMEM (53632 * 4)

__global__ __launch_bounds__(512, 1)
void fused_kernel(const float* __restrict__ x,
                  const float* __restrict__ bout,
                  const float* __restrict__ pe,  const float* __restrict__ ul,
                  const float* __restrict__ lr,  float* __restrict__ out) {
    extern __shared__ uint32_t sm[];
    uint32_t* sQ = sm + SQ_OFF;
    uint32_t* sK = sm + SK_OFF;
    uint32_t* sV = sm + SV_OFF;
    uint32_t* sA = sm + SA_OFF;
    uint32_t* sP = sm + SP_OFF;
    float* sPE = (float*)(sm + PE_OFF);
    float* sBO = (float*)(sm + BO_OFF);

    const int t = threadIdx.x;
    const int warp = t >> 5, lane = t & 31;
    const int gid = lane >> 2, tid4 = lane & 3;
    const int blk = blockIdx.x;
    const int bb = blk >> 8, win = blk & 255;
    const int wy = win >> 4, wx = win & 15;

    // warp role: head h, sub-slice s (24 cols of the 96-col head block)
    const int head = warp >> 2, s = warp & 3;
    const int hoff = head * 32;
    const int wrb = s * 16;                  // attention q-row base

    // B fragment loader: 3 n8'-tiles of this warp's slice
    uint2 bA[6], bB[6];
    auto ldBkt = [&](uint2* dst, int kt) {
        #pragma unroll
        for (int kk = 0; kk < 2; kk++) {
            int step = kt * 2 + kk;
            #pragma unroll
            for (int nt = 0; nt < 3; nt++) {
                int n8p = head * 12 + s * 3 + nt;
                dst[kk * 3 + nt] =
                    *(const uint2*)&g_wqkvF[(n8p * 16 + step) * 64 + lane * 2];
            }
        }
    };
    ldBkt(bA, 0);
    ldBkt(bB, 1);

    // ---- A gather: rolled x rows, tf32, pair-interleaved, packed STS.64 ----
    {
        const int row_a = t >> 3, part = t & 7;
        const int ty = row_a >> 3, tx = row_a & 7;
        const int sh = (wy * 8 + ty + 4) & 127, sw = (wx * 8 + tx + 4) & 127;
        const float* aptr = x + (((size_t)bb * 128 + sh) * 128 + sw) * 128 + part * 16;
        uint32_t* ap = sA + row_a * 136 + part * 16;
        float4 v0 = *(const float4*)(aptr + 0);
        float4 v1 = *(const float4*)(aptr + 4);
        float4 v2 = *(const float4*)(aptr + 8);
        float4 v3 = *(const float4*)(aptr + 12);
        *(uint2*)&ap[0]  = make_uint2(f2tf(v0.x), f2tf(v1.x));
        *(uint2*)&ap[2]  = make_uint2(f2tf(v0.y), f2tf(v1.y));
        *(uint2*)&ap[4]  = make_uint2(f2tf(v0.z), f2tf(v1.z));
        *(uint2*)&ap[6]  = make_uint2(f2tf(v0.w), f2tf(v1.w));
        *(uint2*)&ap[8]  = make_uint2(f2tf(v2.x), f2tf(v3.x));
        *(uint2*)&ap[10] = make_uint2(f2tf(v2.y), f2tf(v3.y));
        *(uint2*)&ap[12] = make_uint2(f2tf(v2.z), f2tf(v3.z));
        *(uint2*)&ap[14] = make_uint2(f2tf(v2.w), f2tf(v3.w));
    }
    if (t < 225) sPE[t] = pe[t];
    if (t < 128) sBO[t] = bout[t];
    __syncthreads();                         // [FULL SYNC 1] sA/sPE/sBO ready

    // ---- Phase 1: QKV slice GEMM, 64 rows x 24 cols per warp ----
    float acc[4][3][4];
    #pragma unroll
    for (int a = 0; a < 4; a++)
        #pragma unroll
        for (int b2 = 0; b2 < 3; b2++)
            #pragma unroll
            for (int c = 0; c < 4; c++) acc[a][b2][c] = 0.f;

    {
        const uint32_t* aR = &sA[gid * 136 + 2 * tid4];
        #pragma unroll
        for (int step = 0; step < 16; step++) {
            const uint2* bfk = (((step >> 1) & 1) ? bB : bA) + (step & 1) * 3;
            uint2 ar[8];
            #pragma unroll
            for (int r = 0; r < 8; r++)
                ar[r] = *(const uint2*)(aR + r * (8 * 136) + step * 8);
            #pragma unroll
            for (int mt = 0; mt < 4; mt++) {
                uint32_t am[4] = {ar[2 * mt].x, ar[2 * mt + 1].x,
                                  ar[2 * mt].y, ar[2 * mt + 1].y};
                #pragma unroll
                for (int nt = 0; nt < 3; nt++)
                    mma8(acc[mt][nt], am, (const uint32_t*)&bfk[nt]);
            }
            if ((step & 1) == 1) {
                int kt = step >> 1;
                if (kt + 2 < 8) ldBkt((kt & 1) ? bB : bA, kt + 2);
            }
        }
    }

    // epilogue: write this warp's 24 cols into sQ/sK/sV (head-local)
    {
        const int s0 = SL(2 * tid4), s1 = SL(2 * tid4 + 1);
        #pragma unroll
        for (int mt = 0; mt < 4; mt++) {
            int r0 = mt * 16 + gid, r1 = r0 + 8;
            #pragma unroll
            for (int nt = 0; nt < 3; nt++) {
                int p = s * 3 + nt;
                int seg = p >> 2;
                int colbase = hoff + (p & 3) * 8;
                uint32_t* dst = sm + (seg == 0 ? SQ_OFF : seg == 1 ? SK_OFF : SV_OFF)
                                   + colbase;
                dst[r0 * 136 + s0] = f2tf(acc[mt][nt][0]);
                dst[r0 * 136 + s1] = f2tf(acc[mt][nt][1]);
                dst[r1 * 136 + s0] = f2tf(acc[mt][nt][2]);
                dst[r1 * 136 + s1] = f2tf(acc[mt][nt][3]);
            }
        }
    }
    // per-head barrier: head h's Q/K/V slice complete
    asm volatile("bar.sync %0, %1;" :: "r"(1 + head), "r"(128) : "memory");

    // ---- Phase B: S = Q K^T (4 warps/head, 16 q-rows each) ----
    float sacc[8][4];
    #pragma unroll
    for (int b2 = 0; b2 < 8; b2++)
        #pragma unroll
        for (int c = 0; c < 4; c++) sacc[b2][c] = 0.f;

    {
        const uint32_t* qR0 = &sQ[(wrb + gid) * 136 + hoff + 2 * tid4];
        const uint32_t* qR1 = qR0 + 8 * 136;
        const uint32_t* kB  = &sK[gid * 136 + hoff + 2 * tid4];
        #pragma unroll
        for (int kk = 0; kk < 32; kk += 8) {
            uint2 a0 = *(const uint2*)(qR0 + kk);
            uint2 a1 = *(const uint2*)(qR1 + kk);
            uint32_t a[4] = {a0.x, a1.x, a0.y, a1.y};
            #pragma unroll
            for (int nt = 0; nt < 8; nt++) {
                uint2 b = *(const uint2*)(kB + nt * (8 * 136) + kk);
                mma8(sacc[nt], a, (const uint32_t*)&b);
            }
        }
    }

    // ---- Phase C: bias + masks + softmax ----
    const float scale = 0.17677669529663689f;
    const bool addUL = (wy == 15);
    const bool addLR = (wx == 15);

    #pragma unroll
    for (int rh = 0; rh < 2; rh++) {
        const int i = wrb + rh * 8 + gid;
        const int iy = i >> 3, ix = i & 7;
        float vrow[16];
        float m = -1e30f;
        #pragma unroll
        for (int nt = 0; nt < 8; nt++) {
            #pragma unroll
            for (int u = 0; u < 2; u++) {
                int j = nt * 8 + tid4 * 2 + u;
                int jy = j >> 3, jx = j & 7;
                float v = sacc[nt][rh * 2 + u] * scale
                        + sPE[(jy - iy + 7) * 15 + (jx - ix + 7)];
                if (addUL) v += ul[i * 64 + j];
                if (addLR) v += lr[i * 64 + j];
                vrow[nt * 2 + u] = v;
                m = fmaxf(m, v);
            }
        }
        m = fmaxf(m, __shfl_xor_sync(0xffffffffu, m, 1));
        m = fmaxf(m, __shfl_xor_sync(0xffffffffu, m, 2));
        float sum = 0.f;
        #pragma unroll
        for (int u2 = 0; u2 < 16; u2++) {
            vrow[u2] = __expf(vrow[u2] - m);
            sum += vrow[u2];
        }
        sum += __shfl_xor_sync(0xffffffffu, sum, 1);
        sum += __shfl_xor_sync(0xffffffffu, sum, 2);
        float inv = 1.f / sum;
        #pragma unroll
        for (int nt = 0; nt < 8; nt++) {
            #pragma unroll
            for (int u = 0; u < 2; u++)
                sacc[nt][rh * 2 + u] = vrow[nt * 2 + u] * inv;
        }
    }

    // ---- Phase D: store P (tf32, paired) into sP[head] ----
    uint32_t* myP = sP + head * (64 * 72);
    {
        const int s0 = SL(2 * tid4), s1 = SL(2 * tid4 + 1);
        #pragma unroll
        for (int rh = 0; rh < 2; rh++) {
            int i = wrb + rh * 8 + gid;
            #pragma unroll
            for (int nt = 0; nt < 8; nt++) {
                myP[i * 72 + nt * 8 + s0] = f2tf(sacc[nt][rh * 2]);
                myP[i * 72 + nt * 8 + s1] = f2tf(sacc[nt][rh * 2 + 1]);
            }
        }
    }
    // per-head barrier: sP[head] coherent for the head's 4 warps
    asm volatile("bar.sync %0, %1;" :: "r"(1 + head), "r"(128) : "memory");

    // ---- Phase E: O = P @ V ----
    float oacc[4][4];
    #pragma unroll
    for (int b2 = 0; b2 < 4; b2++)
        #pragma unroll
        for (int c = 0; c < 4; c++) oacc[b2][c] = 0.f;
    const int dslot = SL(gid);

    {
        const uint32_t* pR0 = &myP[(wrb + gid) * 72 + 2 * tid4];
        const uint32_t* pR1 = pR0 + 8 * 72;
        const uint32_t* vB0 = &sV[tid4 * 136 + hoff + dslot];
        const uint32_t* vB1 = vB0 + 4 * 136;
        #pragma unroll
        for (int kk = 0; kk < 8; kk++) {
            uint2 a0 = *(const uint2*)(pR0 + kk * 8);
            uint2 a1 = *(const uint2*)(pR1 + kk * 8);
            uint32_t a[4] = {a0.x, a1.x, a0.y, a1.y};
            #pragma unroll
            for (int nt = 0; nt < 4; nt++) {
                uint32_t b[2];
                b[0] = vB0[kk * (8 * 136) + nt * 8];
                b[1] = vB1[kk * (8 * 136) + nt * 8];
                mma8(oacc[nt], a, b);
            }
        }
    }

    // ---- Phase F: store O into own rows of sP[head] (P dead for them) ----
    // layout: sP[head][row][group nt (0..3)*8 + paired slot], stride 72
    {
        const int s0 = SL(2 * tid4), s1 = SL(2 * tid4 + 1);
        #pragma unroll
        for (int nt = 0; nt < 4; nt++) {
            myP[(wrb + gid) * 72 + nt * 8 + s0]     = f2tf(oacc[nt][0]);
            myP[(wrb + gid) * 72 + nt * 8 + s1]     = f2tf(oacc[nt][1]);
            myP[(wrb + 8 + gid) * 72 + nt * 8 + s0] = f2tf(oacc[nt][2]);
            myP[(wrb + 8 + gid) * 72 + nt * 8 + s1] = f2tf(oacc[nt][3]);
        }
    }
    __syncthreads();                         // [FULL SYNC 2] all heads' O ready

    // ---- Phase G: Y = O @ w_out + b_out ----
    // O a-frag for k-step kk: head kk>>2, col-group kk&3, from sP region.
    const int pwm = warp & 3, pwn = warp >> 2;   // 4x4 grid, tile 16x32
    float yacc[4][4];
    #pragma unroll
    for (int b2 = 0; b2 < 4; b2++)
        #pragma unroll
        for (int c = 0; c < 4; c++) yacc[b2][c] = 0.f;

    uint2 wA[4], wB[4];
    auto ldW = [&](uint2* dst, int kk) {
        #pragma unroll
        for (int nt = 0; nt < 4; nt++) {
            int n8g = pwn * 4 + nt;
            dst[nt] = *(const uint2*)&g_woutF[(n8g * 16 + kk) * 64 + lane * 2];
        }
    };
    const uint32_t* oBase0 = sP + (pwm * 16 + gid) * 72 + 2 * tid4;
    const uint32_t* oBase1 = oBase0 + 8 * 72;
    auto ldOA = [&](uint2* d, int kk) {
        int off = (kk >> 2) * (64 * 72) + (kk & 3) * 8;
        d[0] = *(const uint2*)(oBase0 + off);
        d[1] = *(const uint2*)(oBase1 + off);
    };
    uint2 oaF[2][2];
    ldW(wA, 0);
    ldW(wB, 1);
    ldOA(oaF[0], 0);

    #pragma unroll
    for (int kk = 0; kk < 16; kk++) {
        if (kk + 1 < 16) ldOA(oaF[(kk + 1) & 1], kk + 1);
        const uint2* wf = (kk & 1) ? wB : wA;
        const uint2* af = oaF[kk & 1];
        uint32_t a[4] = {af[0].x, af[1].x, af[0].y, af[1].y};
        #pragma unroll
        for (int nt = 0; nt < 4; nt++)
            mma8(yacc[nt], a, (const uint32_t*)&wf[nt]);
        if (kk + 2 < 16) {
            if ((kk & 1) == 0) ldW(wA, kk + 2);
            else               ldW(wB, kk + 2);
        }
    }

    #pragma unroll
    for (int rh = 0; rh < 2; rh++) {
        int i = pwm * 16 + rh * 8 + gid;
        int ty = i >> 3, tx = i & 7;
        int h = (wy * 8 + ty + 4) & 127;
        int w = (wx * 8 + tx + 4) & 127;
        float* orow = out + (((size_t)bb * 128 + h) * 128 + w) * 128;
        #pragma unroll
        for (int nt = 0; nt < 4; nt++) {
            int c = pwn * 32 + nt * 8 + tid4 * 2;
            float2 v = make_float2(yacc[nt][rh * 2]     + sBO[c],
                                   yacc[nt][rh * 2 + 1] + sBO[c + 1]);
            *(float2*)(orow + c) = v;
        }
    }
}

// ===========================================================================
extern "C" void kernel_launch(void* const* d_in, const int* in_sizes, int n_in,
                              void* d_out, int out_size) {
    const float* x    = (const float*)d_in[0];
    const float* wqkv = (const float*)d_in[1];
    const float* wout = (const float*)d_in[2];
    const float* bout = (const float*)d_in[3];
    const float* pe   = (const float*)d_in[4];
    const float* ul   = (const float*)d_in[5];
    const float* lr   = (const float*)d_in[6];
    float* out = (float*)d_out;

    cudaFuncSetAttribute(fused_kernel, cudaFuncAttributeMaxDynamicSharedMemorySize, FU_SMEM);

    cvt_kernel<<<192, 256>>>(wqkv, wout);
    fused_kernel<<<4096, 512, FU_SMEM>>>(x, bout, pe, ul, lr, out);
}